// round 10
// baseline (speedup 1.0000x reference)
#include <cuda_runtime.h>
#include <cuda_bf16.h>

// Problem constants (fixed by the dataset):
//   acts: (B, T, U+1, V) fp32, labels: (B, U) int32, act_lens/label_lens: (B,) int32
#define BB  16
#define TT  200
#define UU  100
#define VV  256
#define UP1 101          // U + 1
#define NEG_INF (-1e30f)
#define DMAXN 300        // max diagonals (T-1+U = 299) + 1

// Scratch (no cudaMalloc allowed).
__device__ float    g_blank[BB * TT * UP1];   // (B, T, U+1)
__device__ float    g_emit [BB * TT * UU];    // (B, T, U)
__device__ float    g_perb [BB];              // per-example nll / label_len
__device__ unsigned g_done = 0;               // block-completion counter

// ---------------------------------------------------------------------------
// Kernel 1: fused log-softmax gather, FOUR (b,t,u) nodes per warp (MLP=8
// LDG.128 per lane). Skips nodes outside the live lattice region.
// ---------------------------------------------------------------------------
__global__ __launch_bounds__(256) void rnnt_softmax_kernel(
    const float* __restrict__ acts,
    const int*   __restrict__ labels,
    const int*   __restrict__ act_lens,
    const int*   __restrict__ label_lens)
{
    const int P = BB * TT * UP1;                       // 323200, divisible by 4
    int w    = blockIdx.x * 8 + (threadIdx.x >> 5);    // warp id
    int lane = threadIdx.x & 31;
    int base = w * 4;
    if (base >= P) return;

    int  uu[4], bt[4], bi[4];
    bool L[4];
    #pragma unroll
    for (int j = 0; j < 4; ++j) {
        int n = base + j;
        uu[j] = n % UP1;
        bt[j] = n / UP1;
        int t = bt[j] % TT;
        bi[j] = bt[j] / TT;
        L[j]  = (t < __ldg(act_lens + bi[j])) && (uu[j] <= __ldg(label_lens + bi[j]));
    }
    if (!(L[0] | L[1] | L[2] | L[3])) return;

    float4 A[4], C[4];
    #pragma unroll
    for (int j = 0; j < 4; ++j) {
        A[j] = make_float4(0.f, 0.f, 0.f, 0.f);
        C[j] = A[j];
        if (L[j]) {
            const float4* p = reinterpret_cast<const float4*>(acts)
                            + (size_t)(base + j) * (VV / 4);
            A[j] = p[lane];
            C[j] = p[lane + 32];
        }
    }

    float m[4], s[4];
    #pragma unroll
    for (int j = 0; j < 4; ++j)
        m[j] = fmaxf(fmaxf(fmaxf(A[j].x, A[j].y), fmaxf(A[j].z, A[j].w)),
                     fmaxf(fmaxf(C[j].x, C[j].y), fmaxf(C[j].z, C[j].w)));
    #pragma unroll
    for (int o = 16; o; o >>= 1) {
        #pragma unroll
        for (int j = 0; j < 4; ++j)
            m[j] = fmaxf(m[j], __shfl_xor_sync(0xffffffffu, m[j], o));
    }
    #pragma unroll
    for (int j = 0; j < 4; ++j)
        s[j] = __expf(A[j].x - m[j]) + __expf(A[j].y - m[j])
             + __expf(A[j].z - m[j]) + __expf(A[j].w - m[j])
             + __expf(C[j].x - m[j]) + __expf(C[j].y - m[j])
             + __expf(C[j].z - m[j]) + __expf(C[j].w - m[j]);
    #pragma unroll
    for (int o = 16; o; o >>= 1) {
        #pragma unroll
        for (int j = 0; j < 4; ++j)
            s[j] += __shfl_xor_sync(0xffffffffu, s[j], o);
    }

    if (lane == 0) {
        #pragma unroll
        for (int j = 0; j < 4; ++j) {
            if (!L[j]) continue;
            int n = base + j;
            float logZ = m[j] + __logf(s[j]);
            g_blank[n] = A[j].x - logZ;               // lane0's A.x = blank logit
            if (uu[j] < UU) {
                int lbl  = labels[bi[j] * UU + uu[j]];
                float lv = __ldg(acts + (size_t)n * VV + lbl);
                g_emit[bt[j] * UU + uu[j]] = lv - logZ;
            }
        }
    }
}

// ---------------------------------------------------------------------------
// Kernel 2: per-example forward DP over 4 warps (u = 32*warp + lane), with the
// per-diagonal __syncthreads replaced by a lock-free neighbor mailbox:
// warp w publishes its lane-31 alpha for diagonal d into slots[w][d] as a
// single 64-bit {value, flag} store; warp w+1 polls it with one volatile
// 64-bit load. Full-length mailbox (no wraparound), warps run skewed.
// Final mean-reduction fused via completion counter.
// ---------------------------------------------------------------------------
__global__ __launch_bounds__(128) void rnnt_dp_kernel(
    const int* __restrict__ act_lens,
    const int* __restrict__ label_lens,
    float*     __restrict__ out)
{
    int b   = blockIdx.x;
    int Tl  = act_lens[b];
    int Ul  = label_lens[b];
    int tid = threadIdx.x;
    int w   = tid >> 5;
    int l   = tid & 31;

    extern __shared__ float sm[];
    float* sb = sm;                 // TT * UP1 floats
    float* se = sm + TT * UP1;      // TT * UU  floats
    __shared__ float2 slots[5][DMAXN];   // rows 0..3: warp mailboxes; row 4: dummy (always ready)

    // float4 staging of the live rows (slabs are 16B-aligned per example).
    {
        const float4* gb4 = reinterpret_cast<const float4*>(g_blank + (size_t)b * TT * UP1);
        const float4* ge4 = reinterpret_cast<const float4*>(g_emit  + (size_t)b * TT * UU);
        float4* sb4 = reinterpret_cast<float4*>(sb);
        float4* se4 = reinterpret_cast<float4*>(se);
        int nb4 = (Tl * UP1 + 3) >> 2;
        int ne4 = (Tl * UU  + 3) >> 2;
        for (int i = tid; i < nb4; i += 128) sb4[i] = gb4[i];
        for (int i = tid; i < ne4; i += 128) se4[i] = ge4[i];
    }
    // Mailbox init: flag=1 for the dummy row (w==0's source) and for d=0
    // (diagonal-0 boundary value is NEG_INF for every warp's left neighbor).
    for (int i = tid; i < 5 * DMAXN; i += 128) {
        int r = i / DMAXN, dd = i % DMAXN;
        slots[r][dd] = make_float2(NEG_INF, (r == 4 || dd == 0) ? 1.0f : 0.0f);
    }
    __syncthreads();

    const unsigned F = 0xffffffffu;
    int u  = w * 32 + l;                      // fixed u per lane (0..127)
    int uc = min(u, UU);                      // sb column
    int ue = min(max(u - 1, 0), UU - 1);      // se column
    int srcrow = (w > 0) ? (w - 1) : 4;

    float pp = (u == 0) ? 0.0f : NEG_INF;     // alpha on previous diagonal

    int dmax = (Tl - 1) + Ul;
    for (int d = 1; d <= dmax; ++d) {
        int t  = d - u;
        int tb = min(max(t - 1, 0), TT - 1);
        int te = min(max(t,     0), TT - 1);
        float bvv = sb[tb * UP1 + uc];
        float evv = se[te * UU  + ue];

        // Poll left-neighbor boundary value (uniform across the warp; in the
        // steady state the producer is already ahead, so this is one LDS.64).
        unsigned saddr = (unsigned)__cvta_generic_to_shared(&slots[srcrow][d - 1]);
        float cx, cf;
        do {
            asm volatile("ld.volatile.shared.v2.f32 {%0,%1}, [%2];"
                         : "=f"(cx), "=f"(cf) : "r"(saddr));
        } while (cf == 0.0f);

        float lf = __shfl_up_sync(F, pp, 1);
        lf = (l == 0) ? cx : lf;

        bool vu = (u <= Ul) & (t >= 0) & (t < Tl);
        bool vb = vu & (t >= 1);
        bool vl = vu & (u >= 1);

        float fb = vb ? pp + bvv : NEG_INF;
        float fl = vl ? lf + evv : NEG_INF;
        float mx = fmaxf(fb, fl);
        float mn = fminf(fb, fl);
        float nv = mx + __logf(1.0f + __expf(mn - mx));
        pp = vu ? nv : NEG_INF;

        // Publish this warp's boundary cell for diagonal d (single 64-bit STS).
        if (l == 31 && w < 3) {
            unsigned pa = (unsigned)__cvta_generic_to_shared(&slots[w][d]);
            asm volatile("st.volatile.shared.v2.f32 [%0], {%1,%2};"
                         :: "r"(pa), "f"(pp), "f"(1.0f));
        }
    }

    // Terminal cell: lane with u == Ul holds alpha(Tl-1, Ul) after last diag.
    if (u == Ul) {
        g_perb[b] = -(pp + sb[(Tl - 1) * UP1 + Ul]) / (float)Ul;
        __threadfence();
        unsigned done = atomicAdd(&g_done, 1u);
        if (done == BB - 1) {                 // last example: fold the mean
            __threadfence();
            float s = 0.0f;
            #pragma unroll
            for (int i = 0; i < BB; ++i) s += __ldcg(&g_perb[i]);
            out[0] = s / (float)BB;
            g_done = 0;                       // reset for next graph replay
        }
    }
}

extern "C" void kernel_launch(void* const* d_in, const int* in_sizes, int n_in,
                              void* d_out, int out_size)
{
    const float* acts       = (const float*)d_in[0];
    const int*   labels     = (const int*)  d_in[1];
    const int*   act_lens   = (const int*)  d_in[2];
    const int*   label_lens = (const int*)  d_in[3];
    float*       out        = (float*)d_out;

    const int P     = BB * TT * UP1;          // lattice nodes
    const int quads = P / 4;                  // four nodes per warp
    int blocks = (quads + 7) / 8;             // 8 warps per 256-thread block
    rnnt_softmax_kernel<<<blocks, 256>>>(acts, labels, act_lens, label_lens);

    size_t smem = (size_t)(TT * UP1 + TT * UU) * sizeof(float);  // 160,800 B dynamic
    cudaFuncSetAttribute(rnnt_dp_kernel,
                         cudaFuncAttributeMaxDynamicSharedMemorySize, (int)smem);
    rnnt_dp_kernel<<<BB, 128, smem>>>(act_lens, label_lens, out);
}

// round 11
// speedup vs baseline: 1.1880x; 1.1880x over previous
#include <cuda_runtime.h>
#include <cuda_bf16.h>

// Problem constants (fixed by the dataset):
//   acts: (B, T, U+1, V) fp32, labels: (B, U) int32, act_lens/label_lens: (B,) int32
#define BB  16
#define TT  200
#define UU  100
#define VV  256
#define UP1 101          // U + 1
#define NEG_INF (-1e30f)

// Scratch (no cudaMalloc allowed).
__device__ float    g_blank[BB * TT * UP1];   // (B, T, U+1)
__device__ float    g_emit [BB * TT * UU];    // (B, T, U)
__device__ float    g_perb [BB];              // per-example nll / label_len
__device__ unsigned g_done = 0;               // block-completion counter

// ---------------------------------------------------------------------------
// Kernel 1: fused log-softmax gather, TWO (b,t,u) nodes per warp (MLP=4).
// Skips nodes outside the live lattice region. (Round-9 version: measured at
// the effective-BW roofline; the 4-node variant regressed on reg pressure.)
// ---------------------------------------------------------------------------
__global__ __launch_bounds__(256) void rnnt_softmax_kernel(
    const float* __restrict__ acts,
    const int*   __restrict__ labels,
    const int*   __restrict__ act_lens,
    const int*   __restrict__ label_lens)
{
    const int P = BB * TT * UP1;                       // 323200 (even)
    int w    = blockIdx.x * 8 + (threadIdx.x >> 5);    // warp id
    int lane = threadIdx.x & 31;
    int n0   = w * 2;
    if (n0 >= P) return;
    int n1 = n0 + 1;

    int u0 = n0 % UP1, bt0 = n0 / UP1, t0 = bt0 % TT, b0i = bt0 / TT;
    int u1 = n1 % UP1, bt1 = n1 / UP1, t1 = bt1 % TT, b1i = bt1 / TT;

    bool L0 = (t0 < __ldg(act_lens + b0i)) && (u0 <= __ldg(label_lens + b0i));
    bool L1 = (t1 < __ldg(act_lens + b1i)) && (u1 <= __ldg(label_lens + b1i));
    if (!L0 && !L1) return;

    const float4* p0 = reinterpret_cast<const float4*>(acts) + (size_t)n0 * (VV / 4);
    const float4* p1 = p0 + (VV / 4);

    float4 a0 = {0,0,0,0}, c0 = {0,0,0,0}, a1 = {0,0,0,0}, c1 = {0,0,0,0};
    if (L0) { a0 = p0[lane]; c0 = p0[lane + 32]; }
    if (L1) { a1 = p1[lane]; c1 = p1[lane + 32]; }

    float m0 = fmaxf(fmaxf(fmaxf(a0.x, a0.y), fmaxf(a0.z, a0.w)),
                     fmaxf(fmaxf(c0.x, c0.y), fmaxf(c0.z, c0.w)));
    float m1 = fmaxf(fmaxf(fmaxf(a1.x, a1.y), fmaxf(a1.z, a1.w)),
                     fmaxf(fmaxf(c1.x, c1.y), fmaxf(c1.z, c1.w)));
    #pragma unroll
    for (int o = 16; o; o >>= 1) {
        m0 = fmaxf(m0, __shfl_xor_sync(0xffffffffu, m0, o));
        m1 = fmaxf(m1, __shfl_xor_sync(0xffffffffu, m1, o));
    }

    float s0 = __expf(a0.x - m0) + __expf(a0.y - m0) + __expf(a0.z - m0) + __expf(a0.w - m0)
             + __expf(c0.x - m0) + __expf(c0.y - m0) + __expf(c0.z - m0) + __expf(c0.w - m0);
    float s1 = __expf(a1.x - m1) + __expf(a1.y - m1) + __expf(a1.z - m1) + __expf(a1.w - m1)
             + __expf(c1.x - m1) + __expf(c1.y - m1) + __expf(c1.z - m1) + __expf(c1.w - m1);
    #pragma unroll
    for (int o = 16; o; o >>= 1) {
        s0 += __shfl_xor_sync(0xffffffffu, s0, o);
        s1 += __shfl_xor_sync(0xffffffffu, s1, o);
    }

    if (lane == 0) {
        if (L0) {
            float logZ = m0 + __logf(s0);
            g_blank[n0] = a0.x - logZ;                 // a0.x on lane0 = blank logit
            if (u0 < UU) {
                int lbl  = labels[b0i * UU + u0];
                float lv = __ldg(acts + (size_t)n0 * VV + lbl);
                g_emit[bt0 * UU + u0] = lv - logZ;
            }
        }
        if (L1) {
            float logZ = m1 + __logf(s1);
            g_blank[n1] = a1.x - logZ;
            if (u1 < UU) {
                int lbl  = labels[b1i * UU + u1];
                float lv = __ldg(acts + (size_t)n1 * VV + lbl);
                g_emit[bt1 * UU + u1] = lv - logZ;
            }
        }
    }
}

// One lattice-cell update (branch-free, clamped addresses, masked values).
__device__ __forceinline__ float rnnt_cell(
    float prev_same_u, float left, float bv, float ev,
    bool vu, bool vb, bool vl)
{
    float fb = vb ? prev_same_u + bv : NEG_INF;
    float fl = vl ? left        + ev : NEG_INF;
    float mx = fmaxf(fb, fl);
    float mn = fminf(fb, fl);
    float nv = mx + __logf(1.0f + __expf(mn - mx));
    return vu ? nv : NEG_INF;
}

// ---------------------------------------------------------------------------
// Kernel 2: per-example forward DP over 4 warps (u = 32*warp + lane), with
// TWO diagonals per __syncthreads via ghost cells: each warp publishes its
// lanes-30/31 alphas per phase; the consumer warp redundantly recomputes the
// neighbor's boundary cell (ghost) for the intermediate diagonal, so only one
// barrier is needed per two diagonals. Double-buffered by phase parity.
// Final mean-reduction fused via completion counter.
// ---------------------------------------------------------------------------
__global__ __launch_bounds__(128) void rnnt_dp_kernel(
    const int* __restrict__ act_lens,
    const int* __restrict__ label_lens,
    float*     __restrict__ out)
{
    int b   = blockIdx.x;
    int Tl  = act_lens[b];
    int Ul  = label_lens[b];
    int tid = threadIdx.x;
    int w   = tid >> 5;
    int l   = tid & 31;

    extern __shared__ float sm[];
    float* sb = sm;                 // TT * UP1 floats
    float* se = sm + TT * UP1;      // TT * UU  floats
    __shared__ float2 bd[2][4];     // [parity][warp] = {alpha[d][32w+30], alpha[d][32w+31]}

    // float4 staging of the live rows (slabs are 16B-aligned per example).
    {
        const float4* gb4 = reinterpret_cast<const float4*>(g_blank + (size_t)b * TT * UP1);
        const float4* ge4 = reinterpret_cast<const float4*>(g_emit  + (size_t)b * TT * UU);
        float4* sb4 = reinterpret_cast<float4*>(sb);
        float4* se4 = reinterpret_cast<float4*>(se);
        int nb4 = (Tl * UP1 + 3) >> 2;
        int ne4 = (Tl * UU  + 3) >> 2;
        for (int i = tid; i < nb4; i += 128) sb4[i] = gb4[i];
        for (int i = tid; i < ne4; i += 128) se4[i] = ge4[i];
    }
    // Phase-0 reads bd[0][*]: boundary alphas on diagonal 0 (u>=30 -> NEG_INF).
    if (tid < 8) bd[tid >> 2][tid & 3] = make_float2(NEG_INF, NEG_INF);
    __syncthreads();

    const unsigned F = 0xffffffffu;
    int u  = w * 32 + l;                      // fixed u per lane (0..127)
    int uc = min(u, UU);                      // sb column
    int ue = min(max(u - 1, 0), UU - 1);      // se column

    // Ghost column: the neighbor warp's last cell u_g = 32w - 1.
    int ug  = w * 32 - 1;
    int ugc = min(max(ug, 0), UU);
    int uge = min(max(ug - 1, 0), UU - 1);
    bool gvalid_u = (w > 0) && (ug <= Ul);    // ug >= 31 >= 1 when w > 0

    float pp = (u == 0) ? 0.0f : NEG_INF;     // alpha on the last computed diagonal

    int dmax = (Tl - 1) + Ul;
    int d    = 1;
    int par  = 0;
    while (d + 1 <= dmax) {
        // Neighbor boundary pair on diagonal d-1 (smem broadcast).
        float2 nb = (w > 0) ? bd[par][w - 1] : make_float2(NEG_INF, NEG_INF);

        // ---- diagonal d ----
        int t1 = d - u;
        {
            int tb = min(max(t1 - 1, 0), TT - 1);
            int te = min(max(t1,     0), TT - 1);
            float bv = sb[tb * UP1 + uc];
            float ev = se[te * UU  + ue];
            bool vu = (u <= Ul) & (t1 >= 0) & (t1 < Tl);
            float lf = __shfl_up_sync(F, pp, 1);
            lf = (l == 0) ? nb.y : lf;
            pp = rnnt_cell(pp, lf, bv, ev, vu, vu & (t1 >= 1), vu & (u >= 1));
        }
        // Ghost cell a[d][32w-1] (parallel to the lane cell; all lanes redundant).
        float g1;
        {
            int tg = d - ug;
            int tb = min(max(tg - 1, 0), TT - 1);
            int te = min(max(tg,     0), TT - 1);
            float bv = sb[tb * UP1 + ugc];
            float ev = se[te * UU  + uge];
            bool vu = gvalid_u & (tg >= 0) & (tg < Tl);
            g1 = rnnt_cell(nb.y, nb.x, bv, ev, vu, vu & (tg >= 1), vu);
        }
        // ---- diagonal d+1 ----
        int t2 = t1 + 1;
        {
            int tb = min(max(t2 - 1, 0), TT - 1);
            int te = min(max(t2,     0), TT - 1);
            float bv = sb[tb * UP1 + uc];
            float ev = se[te * UU  + ue];
            bool vu = (u <= Ul) & (t2 >= 0) & (t2 < Tl);
            float lf = __shfl_up_sync(F, pp, 1);
            lf = (l == 0) ? g1 : lf;
            pp = rnnt_cell(pp, lf, bv, ev, vu, vu & (t2 >= 1), vu & (u >= 1));
        }
        // Publish lanes 30/31 alphas at diagonal d+1 into the opposite buffer.
        if (l >= 30 && w < 3)
            reinterpret_cast<float*>(&bd[par ^ 1][w])[l - 30] = pp;
        par ^= 1;
        d += 2;
        __syncthreads();
    }
    if (d == dmax) {                          // odd tail: one last diagonal
        float2 nb = (w > 0) ? bd[par][w - 1] : make_float2(NEG_INF, NEG_INF);
        int t1 = d - u;
        int tb = min(max(t1 - 1, 0), TT - 1);
        int te = min(max(t1,     0), TT - 1);
        float bv = sb[tb * UP1 + uc];
        float ev = se[te * UU  + ue];
        bool vu = (u <= Ul) & (t1 >= 0) & (t1 < Tl);
        float lf = __shfl_up_sync(F, pp, 1);
        lf = (l == 0) ? nb.y : lf;
        pp = rnnt_cell(pp, lf, bv, ev, vu, vu & (t1 >= 1), vu & (u >= 1));
    }

    // Terminal cell: lane with u == Ul holds alpha(Tl-1, Ul).
    if (u == Ul) {
        g_perb[b] = -(pp + sb[(Tl - 1) * UP1 + Ul]) / (float)Ul;
        __threadfence();
        unsigned done = atomicAdd(&g_done, 1u);
        if (done == BB - 1) {                 // last example: fold the mean
            __threadfence();
            float s = 0.0f;
            #pragma unroll
            for (int i = 0; i < BB; ++i) s += __ldcg(&g_perb[i]);
            out[0] = s / (float)BB;
            g_done = 0;                       // reset for next graph replay
        }
    }
}

extern "C" void kernel_launch(void* const* d_in, const int* in_sizes, int n_in,
                              void* d_out, int out_size)
{
    const float* acts       = (const float*)d_in[0];
    const int*   labels     = (const int*)  d_in[1];
    const int*   act_lens   = (const int*)  d_in[2];
    const int*   label_lens = (const int*)  d_in[3];
    float*       out        = (float*)d_out;

    const int P     = BB * TT * UP1;          // lattice nodes
    const int pairs = P / 2;                  // two nodes per warp
    int blocks = (pairs + 7) / 8;             // 8 warps per 256-thread block
    rnnt_softmax_kernel<<<blocks, 256>>>(acts, labels, act_lens, label_lens);

    size_t smem = (size_t)(TT * UP1 + TT * UU) * sizeof(float);  // 160,800 B dynamic
    cudaFuncSetAttribute(rnnt_dp_kernel,
                         cudaFuncAttributeMaxDynamicSharedMemorySize, (int)smem);
    rnnt_dp_kernel<<<BB, 128, smem>>>(act_lens, label_lens, out);
}